// round 3
// baseline (speedup 1.0000x reference)
#include <cuda_runtime.h>
#include <cuda_bf16.h>
#include <cstdint>

#define N_USER 100000
#define N_BOOK 50000
#define N_EDGE 1000000
#define HID    128
#define N_TOT  (N_USER + N_BOOK)

// -------- scratch (no cudaMalloc allowed) --------
__device__ float g_sum_user[(size_t)N_USER * HID];   // sum of book features per user
__device__ float g_sum_book[(size_t)N_BOOK * HID];   // sum of user features per book
__device__ int   g_cnt_user[N_USER];
__device__ int   g_cnt_book[N_BOOK];

// ---------------- zero scratch ----------------
__global__ void zero_kernel() {
    long i = (long)blockIdx.x * blockDim.x + threadIdx.x;
    long stride = (long)gridDim.x * blockDim.x;
    const long n1 = (long)N_USER * HID / 4;
    const long n2 = (long)N_BOOK * HID / 4;
    float4 z = make_float4(0.f, 0.f, 0.f, 0.f);
    float4* su = (float4*)g_sum_user;
    float4* sb = (float4*)g_sum_book;
    for (long j = i; j < n1; j += stride) su[j] = z;
    for (long j = i; j < n2; j += stride) sb[j] = z;
    for (long j = i; j < N_USER; j += stride) g_cnt_user[j] = 0;
    for (long j = i; j < N_BOOK; j += stride) g_cnt_book[j] = 0;
}

// ---------------- scatter-add (both directions), one warp per edge ----------------
__device__ __forceinline__ void red_add4(float* addr, float4 v) {
    asm volatile("red.global.add.v4.f32 [%0], {%1,%2,%3,%4};"
                 :: "l"(addr), "f"(v.x), "f"(v.y), "f"(v.z), "f"(v.w)
                 : "memory");
}

__global__ void scatter_kernel(const float* __restrict__ x_user,
                               const float* __restrict__ x_book,
                               const int*   __restrict__ edge_src,
                               const int*   __restrict__ edge_dst) {
    int warp  = (blockIdx.x * blockDim.x + threadIdx.x) >> 5;
    int lane  = threadIdx.x & 31;
    int nwarp = (gridDim.x * blockDim.x) >> 5;
    for (int e = warp; e < N_EDGE; e += nwarp) {
        int s = edge_src[e];
        int d = edge_dst[e];
        float4 vu = __ldg((const float4*)(x_user + (size_t)s * HID) + lane);
        float4 vb = __ldg((const float4*)(x_book + (size_t)d * HID) + lane);
        red_add4(g_sum_book + (size_t)d * HID + lane * 4, vu);
        red_add4(g_sum_user + (size_t)s * HID + lane * 4, vb);
        if (lane == 0)      atomicAdd(&g_cnt_book[d], 1);
        else if (lane == 1) atomicAdd(&g_cnt_user[s], 1);
    }
}

// ---------------- fused GEMM: out = relu([agg | x] @ [Wl;Wr]^T + bl) ----------------
// Combined K = 256 (k<128 -> normalized agg, k>=128 -> root features x).
// Rows 0..N_USER-1 are users, N_USER..N_TOT-1 are books; output layout matches.
#define TM 64
#define WS_STRIDE 132              // 128 + 4 pad, keeps float4 alignment
#define AS_STRIDE 36               // 32 + 4 pad
#define GEMM_SMEM ((256 * WS_STRIDE + TM * AS_STRIDE) * 4)

__global__ void gemm_kernel(const float* __restrict__ x_user,
                            const float* __restrict__ x_book,
                            const float* __restrict__ Wl,
                            const float* __restrict__ Wr,
                            const float* __restrict__ bl,
                            float* __restrict__ out) {
    extern __shared__ float sm[];
    float* Ws = sm;                      // [256][WS_STRIDE] : Ws[k][c] = W2[c][k]
    float* As = sm + 256 * WS_STRIDE;    // [TM][AS_STRIDE]

    int tid = threadIdx.x;

    // Fill Ws: global reads coalesced over k (rows of Wl/Wr are contiguous in k).
    for (int i = tid; i < 128 * 128; i += 256) {
        int c = i >> 7, k = i & 127;
        float wl = __ldg(Wl + i);            // Wl[c][k]
        float wr = __ldg(Wr + i);            // Wr[c][k]
        Ws[k * WS_STRIDE + c]         = wl;
        Ws[(k + 128) * WS_STRIDE + c] = wr;
    }
    __syncthreads();

    int rowbase = blockIdx.x * TM;
    int ty = tid >> 4;          // 0..15 -> 4 rows each
    int tx = tid & 15;          // 0..15 -> 8 contiguous cols each

    float acc[4][8];
#pragma unroll
    for (int i = 0; i < 4; i++)
#pragma unroll
        for (int j = 0; j < 8; j++) acc[i][j] = 0.f;

    for (int ch = 0; ch < 8; ch++) {
        int k0 = ch * 32;
        __syncthreads();
        // Load A tile: 64 rows x 32 k. 256 threads: 2 passes of 32 rows, 8 float4/row.
#pragma unroll
        for (int p = 0; p < 2; p++) {
            int rl = p * 32 + (tid >> 3);
            int r  = rowbase + rl;
            int kk = (tid & 7) * 4;
            float4 v = make_float4(0.f, 0.f, 0.f, 0.f);
            if (r < N_TOT) {
                if (k0 < 128) {                       // aggregated (mean) part
                    if (r < N_USER) {
                        v = *(const float4*)(g_sum_user + (size_t)r * HID + k0 + kk);
                        float inv = 1.0f / fmaxf((float)g_cnt_user[r], 1.0f);
                        v.x *= inv; v.y *= inv; v.z *= inv; v.w *= inv;
                    } else {
                        int rb = r - N_USER;
                        v = *(const float4*)(g_sum_book + (size_t)rb * HID + k0 + kk);
                        float inv = 1.0f / fmaxf((float)g_cnt_book[rb], 1.0f);
                        v.x *= inv; v.y *= inv; v.z *= inv; v.w *= inv;
                    }
                } else {                              // root feature part
                    int k2 = k0 - 128 + kk;
                    if (r < N_USER)
                        v = __ldg((const float4*)(x_user + (size_t)r * HID + k2));
                    else
                        v = __ldg((const float4*)(x_book + (size_t)(r - N_USER) * HID + k2));
                }
            }
            *(float4*)(As + rl * AS_STRIDE + kk) = v;
        }
        __syncthreads();

#pragma unroll 4
        for (int kk = 0; kk < 32; kk++) {
            int k = k0 + kk;
            const float4 w0 = *(const float4*)(Ws + k * WS_STRIDE + tx * 8);
            const float4 w1 = *(const float4*)(Ws + k * WS_STRIDE + tx * 8 + 4);
            float a[4];
#pragma unroll
            for (int i = 0; i < 4; i++) a[i] = As[(ty * 4 + i) * AS_STRIDE + kk];
#pragma unroll
            for (int i = 0; i < 4; i++) {
                acc[i][0] += a[i] * w0.x;
                acc[i][1] += a[i] * w0.y;
                acc[i][2] += a[i] * w0.z;
                acc[i][3] += a[i] * w0.w;
                acc[i][4] += a[i] * w1.x;
                acc[i][5] += a[i] * w1.y;
                acc[i][6] += a[i] * w1.z;
                acc[i][7] += a[i] * w1.w;
            }
        }
    }

    // Epilogue: bias + ReLU, write fp32 output (users then books == row order).
    int cbase = tx * 8;
    float b[8];
#pragma unroll
    for (int j = 0; j < 8; j++) b[j] = __ldg(bl + cbase + j);
#pragma unroll
    for (int i = 0; i < 4; i++) {
        int r = rowbase + ty * 4 + i;
        if (r < N_TOT) {
            float4 o0, o1;
            o0.x = fmaxf(acc[i][0] + b[0], 0.f);
            o0.y = fmaxf(acc[i][1] + b[1], 0.f);
            o0.z = fmaxf(acc[i][2] + b[2], 0.f);
            o0.w = fmaxf(acc[i][3] + b[3], 0.f);
            o1.x = fmaxf(acc[i][4] + b[4], 0.f);
            o1.y = fmaxf(acc[i][5] + b[5], 0.f);
            o1.z = fmaxf(acc[i][6] + b[6], 0.f);
            o1.w = fmaxf(acc[i][7] + b[7], 0.f);
            *(float4*)(out + (size_t)r * HID + cbase)     = o0;
            *(float4*)(out + (size_t)r * HID + cbase + 4) = o1;
        }
    }
}

extern "C" void kernel_launch(void* const* d_in, const int* in_sizes, int n_in,
                              void* d_out, int out_size) {
    const float* x_user   = (const float*)d_in[0];
    const float* x_book   = (const float*)d_in[1];
    const int*   edge_src = (const int*)  d_in[2];
    const int*   edge_dst = (const int*)  d_in[3];
    const float* Wl       = (const float*)d_in[4];
    const float* bl       = (const float*)d_in[5];
    const float* Wr       = (const float*)d_in[6];
    float* out = (float*)d_out;

    static bool attr_set = false;
    if (!attr_set) {
        cudaFuncSetAttribute(gemm_kernel,
                             cudaFuncAttributeMaxDynamicSharedMemorySize, GEMM_SMEM);
        attr_set = true;
    }

    zero_kernel<<<1024, 256>>>();
    scatter_kernel<<<8192, 256>>>(x_user, x_book, edge_src, edge_dst);
    int gemm_blocks = (N_TOT + TM - 1) / TM;
    gemm_kernel<<<gemm_blocks, 256, GEMM_SMEM>>>(x_user, x_book, Wl, Wr, bl, out);
}

// round 9
// speedup vs baseline: 1.2396x; 1.2396x over previous
#include <cuda_runtime.h>
#include <cuda_bf16.h>
#include <cstdint>

#define N_USER 100000
#define N_BOOK 50000
#define N_EDGE 1000000
#define HID    128
#define N_TOT  (N_USER + N_BOOK)

// -------- scratch (no cudaMalloc allowed) --------
// NOTE: these symbols must ONLY be referenced from device code. Passing them
// as kernel arguments from host code yields the host shadow address (silently
// writable on GB300 via ATS!) — that was the R4/R8 correctness bug.
__device__ float g_sum_user[(size_t)N_USER * HID];   // sum of book features per user
__device__ float g_sum_book[(size_t)N_BOOK * HID];   // sum of user features per book
__device__ int   g_cnt_user[N_USER];
__device__ int   g_cnt_book[N_BOOK];

// ---------------- zero scratch ----------------
__global__ void zero_kernel() {
    long i = (long)blockIdx.x * blockDim.x + threadIdx.x;
    long stride = (long)gridDim.x * blockDim.x;
    const long n1 = (long)N_USER * HID / 4;
    const long n2 = (long)N_BOOK * HID / 4;
    float4 z = make_float4(0.f, 0.f, 0.f, 0.f);
    float4* su = (float4*)g_sum_user;
    float4* sb = (float4*)g_sum_book;
    for (long j = i; j < n1; j += stride) su[j] = z;
    for (long j = i; j < n2; j += stride) sb[j] = z;
    for (long j = i; j < N_USER; j += stride) g_cnt_user[j] = 0;
    for (long j = i; j < N_BOOK; j += stride) g_cnt_book[j] = 0;
}

// ---------------- scatter-add, one direction per pass (L2 locality) ----------------
__device__ __forceinline__ void red_add4(float* addr, float4 v) {
    asm volatile("red.global.add.v4.f32 [%0], {%1,%2,%3,%4};"
                 :: "l"(addr), "f"(v.x), "f"(v.y), "f"(v.z), "f"(v.w)
                 : "memory");
}

// dir == 0: user -> book (gather x_user[src], accumulate into g_sum_book[dst])
// dir == 1: book -> user (gather x_book[src], accumulate into g_sum_user[dst])
// Scratch symbols resolved in DEVICE code so we get true device addresses.
__global__ void scatter_dir_kernel(const float* __restrict__ xsrc,
                                   const int*   __restrict__ src_idx,
                                   const int*   __restrict__ dst_idx,
                                   int dir) {
    float* __restrict__ sum_dst = dir ? g_sum_user : g_sum_book;
    int*   __restrict__ cnt_dst = dir ? g_cnt_user : g_cnt_book;
    int warp  = (blockIdx.x * blockDim.x + threadIdx.x) >> 5;
    int lane  = threadIdx.x & 31;
    int nwarp = (gridDim.x * blockDim.x) >> 5;
    for (int e = warp; e < N_EDGE; e += nwarp) {
        int s = __ldg(src_idx + e);
        int d = __ldg(dst_idx + e);
        float4 v = __ldg((const float4*)(xsrc + (size_t)s * HID) + lane);
        red_add4(sum_dst + (size_t)d * HID + lane * 4, v);
        if (lane == 0) atomicAdd(&cnt_dst[d], 1);
    }
}

// ---------------- fused GEMM: out = relu([agg | x] @ [Wl;Wr]^T + bl) ----------------
// Combined K = 256 (k<128 -> normalized agg, k>=128 -> root features x).
// Scalar FFMA inner loop (proven correct in R3); TM=128 tile, 512 threads.
#define TM 128
#define GTHREADS 512
#define WS_STRIDE 132              // 128 + 4 pad, keeps 16B alignment per k-row
#define AS_STRIDE 36               // 32 + 4 pad
#define GEMM_SMEM ((256 * WS_STRIDE + TM * AS_STRIDE) * 4)

__global__ __launch_bounds__(GTHREADS, 1)
void gemm_kernel(const float* __restrict__ x_user,
                 const float* __restrict__ x_book,
                 const float* __restrict__ Wl,
                 const float* __restrict__ Wr,
                 const float* __restrict__ bl,
                 float* __restrict__ out) {
    extern __shared__ float sm[];
    float* Ws = sm;                      // [256][WS_STRIDE] : Ws[k][c] = W2[c][k]
    float* As = sm + 256 * WS_STRIDE;    // [TM][AS_STRIDE]

    int tid = threadIdx.x;

    // Fill Ws: global reads coalesced over k (rows of Wl/Wr are contiguous in k).
    for (int i = tid; i < 128 * 128; i += GTHREADS) {
        int c = i >> 7, k = i & 127;
        float wl = __ldg(Wl + i);            // Wl[c][k]
        float wr = __ldg(Wr + i);            // Wr[c][k]
        Ws[k * WS_STRIDE + c]         = wl;
        Ws[(k + 128) * WS_STRIDE + c] = wr;
    }
    __syncthreads();

    int rowbase = blockIdx.x * TM;
    int ty = tid >> 4;          // 0..31 -> 4 rows each
    int tx = tid & 15;          // 0..15 -> 8 contiguous cols each

    float acc[4][8];
#pragma unroll
    for (int i = 0; i < 4; i++)
#pragma unroll
        for (int j = 0; j < 8; j++) acc[i][j] = 0.f;

    for (int ch = 0; ch < 8; ch++) {
        int k0 = ch * 32;
        __syncthreads();
        // Load A tile: 128 rows x 32 k. 512 threads: 2 passes of 64 rows, 8 float4/row.
#pragma unroll
        for (int p = 0; p < 2; p++) {
            int rl = p * 64 + (tid >> 3);
            int r  = rowbase + rl;
            int kk = (tid & 7) * 4;
            float4 v = make_float4(0.f, 0.f, 0.f, 0.f);
            if (r < N_TOT) {
                if (k0 < 128) {                       // aggregated (mean) part
                    if (r < N_USER) {
                        v = *(const float4*)(g_sum_user + (size_t)r * HID + k0 + kk);
                        float inv = 1.0f / fmaxf((float)g_cnt_user[r], 1.0f);
                        v.x *= inv; v.y *= inv; v.z *= inv; v.w *= inv;
                    } else {
                        int rb = r - N_USER;
                        v = *(const float4*)(g_sum_book + (size_t)rb * HID + k0 + kk);
                        float inv = 1.0f / fmaxf((float)g_cnt_book[rb], 1.0f);
                        v.x *= inv; v.y *= inv; v.z *= inv; v.w *= inv;
                    }
                } else {                              // root feature part
                    int k2 = k0 - 128 + kk;
                    if (r < N_USER)
                        v = __ldg((const float4*)(x_user + (size_t)r * HID + k2));
                    else
                        v = __ldg((const float4*)(x_book + (size_t)(r - N_USER) * HID + k2));
                }
            }
            *(float4*)(As + rl * AS_STRIDE + kk) = v;
        }
        __syncthreads();

#pragma unroll 4
        for (int kk = 0; kk < 32; kk++) {
            int k = k0 + kk;
            const float4 w0 = *(const float4*)(Ws + k * WS_STRIDE + tx * 8);
            const float4 w1 = *(const float4*)(Ws + k * WS_STRIDE + tx * 8 + 4);
            float a[4];
#pragma unroll
            for (int i = 0; i < 4; i++) a[i] = As[(ty * 4 + i) * AS_STRIDE + kk];
#pragma unroll
            for (int i = 0; i < 4; i++) {
                acc[i][0] += a[i] * w0.x;
                acc[i][1] += a[i] * w0.y;
                acc[i][2] += a[i] * w0.z;
                acc[i][3] += a[i] * w0.w;
                acc[i][4] += a[i] * w1.x;
                acc[i][5] += a[i] * w1.y;
                acc[i][6] += a[i] * w1.z;
                acc[i][7] += a[i] * w1.w;
            }
        }
    }

    // Epilogue: bias + ReLU, write fp32 output (users then books == row order).
    int cbase = tx * 8;
    float b[8];
#pragma unroll
    for (int j = 0; j < 8; j++) b[j] = __ldg(bl + cbase + j);
#pragma unroll
    for (int i = 0; i < 4; i++) {
        int r = rowbase + ty * 4 + i;
        if (r < N_TOT) {
            float4 o0, o1;
            o0.x = fmaxf(acc[i][0] + b[0], 0.f);
            o0.y = fmaxf(acc[i][1] + b[1], 0.f);
            o0.z = fmaxf(acc[i][2] + b[2], 0.f);
            o0.w = fmaxf(acc[i][3] + b[3], 0.f);
            o1.x = fmaxf(acc[i][4] + b[4], 0.f);
            o1.y = fmaxf(acc[i][5] + b[5], 0.f);
            o1.z = fmaxf(acc[i][6] + b[6], 0.f);
            o1.w = fmaxf(acc[i][7] + b[7], 0.f);
            *(float4*)(out + (size_t)r * HID + cbase)     = o0;
            *(float4*)(out + (size_t)r * HID + cbase + 4) = o1;
        }
    }
}

extern "C" void kernel_launch(void* const* d_in, const int* in_sizes, int n_in,
                              void* d_out, int out_size) {
    const float* x_user   = (const float*)d_in[0];
    const float* x_book   = (const float*)d_in[1];
    const int*   edge_src = (const int*)  d_in[2];
    const int*   edge_dst = (const int*)  d_in[3];
    const float* Wl       = (const float*)d_in[4];
    const float* bl       = (const float*)d_in[5];
    const float* Wr       = (const float*)d_in[6];
    float* out = (float*)d_out;

    static bool attr_set = false;
    if (!attr_set) {
        cudaFuncSetAttribute(gemm_kernel,
                             cudaFuncAttributeMaxDynamicSharedMemorySize, GEMM_SMEM);
        attr_set = true;
    }

    zero_kernel<<<1024, 256>>>();
    // Pass 1: user -> book. Working set x_user (51MB) + g_sum_book (26MB) fits L2.
    scatter_dir_kernel<<<8192, 256>>>(x_user, edge_src, edge_dst, /*dir=*/0);
    // Pass 2: book -> user. Working set x_book (26MB) + g_sum_user (51MB) fits L2.
    scatter_dir_kernel<<<8192, 256>>>(x_book, edge_dst, edge_src, /*dir=*/1);
    int gemm_blocks = (N_TOT + TM - 1) / TM;
    gemm_kernel<<<gemm_blocks, GTHREADS, GEMM_SMEM>>>(x_user, x_book, Wl, Wr, bl, out);
}

// round 10
// speedup vs baseline: 1.3662x; 1.1021x over previous
#include <cuda_runtime.h>
#include <cuda_bf16.h>
#include <cstdint>

#define N_USER 100000
#define N_BOOK 50000
#define N_EDGE 1000000
#define HID    128
#define N_TOT  (N_USER + N_BOOK)

// -------- scratch (no cudaMalloc allowed) --------
// NOTE: these symbols must ONLY be referenced from device code. Passing them
// as kernel arguments from host code yields the host shadow address (silently
// writable on GB300 via ATS!) — that was the R4/R8 correctness bug.
__device__ float g_sum_user[(size_t)N_USER * HID];   // sum of book features per user
__device__ float g_sum_book[(size_t)N_BOOK * HID];   // sum of user features per book
__device__ int   g_cnt_user[N_USER];
__device__ int   g_cnt_book[N_BOOK];

// ---------------- zero scratch ----------------
__global__ void zero_kernel() {
    long i = (long)blockIdx.x * blockDim.x + threadIdx.x;
    long stride = (long)gridDim.x * blockDim.x;
    const long n1 = (long)N_USER * HID / 4;
    const long n2 = (long)N_BOOK * HID / 4;
    float4 z = make_float4(0.f, 0.f, 0.f, 0.f);
    float4* su = (float4*)g_sum_user;
    float4* sb = (float4*)g_sum_book;
    for (long j = i; j < n1; j += stride) su[j] = z;
    for (long j = i; j < n2; j += stride) sb[j] = z;
    for (long j = i; j < N_USER; j += stride) g_cnt_user[j] = 0;
    for (long j = i; j < N_BOOK; j += stride) g_cnt_book[j] = 0;
}

// ---------------- scatter-add, one direction per pass (L2 locality) ----------------
__device__ __forceinline__ void red_add4(float* addr, float4 v) {
    asm volatile("red.global.add.v4.f32 [%0], {%1,%2,%3,%4};"
                 :: "l"(addr), "f"(v.x), "f"(v.y), "f"(v.z), "f"(v.w)
                 : "memory");
}

// dir == 0: user -> book; dir == 1: book -> user.
// Scratch symbols resolved in DEVICE code so we get true device addresses.
__global__ void scatter_dir_kernel(const float* __restrict__ xsrc,
                                   const int*   __restrict__ src_idx,
                                   const int*   __restrict__ dst_idx,
                                   int dir) {
    float* __restrict__ sum_dst = dir ? g_sum_user : g_sum_book;
    int*   __restrict__ cnt_dst = dir ? g_cnt_user : g_cnt_book;
    int warp  = (blockIdx.x * blockDim.x + threadIdx.x) >> 5;
    int lane  = threadIdx.x & 31;
    int nwarp = (gridDim.x * blockDim.x) >> 5;
    for (int e = warp; e < N_EDGE; e += nwarp) {
        int s = __ldg(src_idx + e);
        int d = __ldg(dst_idx + e);
        float4 v = __ldg((const float4*)(xsrc + (size_t)s * HID) + lane);
        red_add4(sum_dst + (size_t)d * HID + lane * 4, v);
        if (lane == 0) atomicAdd(&cnt_dst[d], 1);
    }
}

// ---------------- fused GEMM: out = relu([agg | x] @ [Wl;Wr]^T + bl) ----------------
// Combined K = 256 (k<128 -> normalized agg, k>=128 -> root features x).
// k-chunked weight tile (32 k-rows resident, 34KB total SMEM) + transposed A
// tile (one LDS.128 per k for the 4 row values) + launch_bounds(512,2) for
// 2 blocks/SM = 32 warps.
#define TM 128
#define KC 32
#define GTHREADS 512
#define TS 132              // padded stride for both [KC][128] tiles

__global__ __launch_bounds__(GTHREADS, 2)
void gemm_kernel(const float* __restrict__ x_user,
                 const float* __restrict__ x_book,
                 const float* __restrict__ Wl,
                 const float* __restrict__ Wr,
                 const float* __restrict__ bl,
                 float* __restrict__ out) {
    __shared__ float Wc[KC * TS];   // Wc[kk][c]  : weights for current k chunk
    __shared__ float At[KC * TS];   // At[kk][row]: A tile transposed

    int tid = threadIdx.x;
    int rowbase = blockIdx.x * TM;
    int ty = tid >> 4;          // 0..31 -> 4 rows each
    int tx = tid & 15;          // 0..15 -> 8 contiguous cols each

    float acc[4][8];
#pragma unroll
    for (int i = 0; i < 4; i++)
#pragma unroll
        for (int j = 0; j < 8; j++) acc[i][j] = 0.f;

    for (int ch = 0; ch < 8; ch++) {
        int k0 = ch * KC;
        __syncthreads();

        // ---- Load weight chunk: Wc[kk][c] = W[c][k0+kk] (W = Wl for k<128 else Wr).
        // 128 cols x 32 k = 1024 float4 along k; 512 threads -> 2 iters.
        {
            const float* Wsrc = (k0 < 128) ? Wl : Wr;
            int kb = k0 & 127;
#pragma unroll
            for (int it = 0; it < 2; it++) {
                int i = it * GTHREADS + tid;
                int c  = i >> 3;
                int kg = (i & 7) * 4;
                float4 w = __ldg((const float4*)(Wsrc + c * HID + kb + kg));
                Wc[(kg + 0) * TS + c] = w.x;
                Wc[(kg + 1) * TS + c] = w.y;
                Wc[(kg + 2) * TS + c] = w.z;
                Wc[(kg + 3) * TS + c] = w.w;
            }
        }

        // ---- Load A tile transposed: At[kk][rl]. 128 rows x 32 k.
#pragma unroll
        for (int p = 0; p < 2; p++) {
            int rl = p * 64 + (tid >> 3);
            int r  = rowbase + rl;
            int kk = (tid & 7) * 4;
            float4 v = make_float4(0.f, 0.f, 0.f, 0.f);
            if (r < N_TOT) {
                if (k0 < 128) {                       // aggregated (mean) part
                    if (r < N_USER) {
                        v = *(const float4*)(g_sum_user + (size_t)r * HID + k0 + kk);
                        float inv = 1.0f / fmaxf((float)g_cnt_user[r], 1.0f);
                        v.x *= inv; v.y *= inv; v.z *= inv; v.w *= inv;
                    } else {
                        int rb = r - N_USER;
                        v = *(const float4*)(g_sum_book + (size_t)rb * HID + k0 + kk);
                        float inv = 1.0f / fmaxf((float)g_cnt_book[rb], 1.0f);
                        v.x *= inv; v.y *= inv; v.z *= inv; v.w *= inv;
                    }
                } else {                              // root feature part
                    int k2 = k0 - 128 + kk;
                    if (r < N_USER)
                        v = __ldg((const float4*)(x_user + (size_t)r * HID + k2));
                    else
                        v = __ldg((const float4*)(x_book + (size_t)(r - N_USER) * HID + k2));
                }
            }
            At[(kk + 0) * TS + rl] = v.x;
            At[(kk + 1) * TS + rl] = v.y;
            At[(kk + 2) * TS + rl] = v.z;
            At[(kk + 3) * TS + rl] = v.w;
        }
        __syncthreads();

        // ---- Inner product: 3 LDS.128 per k (a4 broadcast + 2 weight vectors).
#pragma unroll 4
        for (int kk = 0; kk < KC; kk++) {
            const float4 a4 = *(const float4*)(At + kk * TS + ty * 4);
            const float4 w0 = *(const float4*)(Wc + kk * TS + tx * 8);
            const float4 w1 = *(const float4*)(Wc + kk * TS + tx * 8 + 4);
            const float a[4] = {a4.x, a4.y, a4.z, a4.w};
#pragma unroll
            for (int i = 0; i < 4; i++) {
                acc[i][0] += a[i] * w0.x;
                acc[i][1] += a[i] * w0.y;
                acc[i][2] += a[i] * w0.z;
                acc[i][3] += a[i] * w0.w;
                acc[i][4] += a[i] * w1.x;
                acc[i][5] += a[i] * w1.y;
                acc[i][6] += a[i] * w1.z;
                acc[i][7] += a[i] * w1.w;
            }
        }
    }

    // Epilogue: bias + ReLU, write fp32 output (users then books == row order).
    int cbase = tx * 8;
    float b[8];
#pragma unroll
    for (int j = 0; j < 8; j++) b[j] = __ldg(bl + cbase + j);
#pragma unroll
    for (int i = 0; i < 4; i++) {
        int r = rowbase + ty * 4 + i;
        if (r < N_TOT) {
            float4 o0, o1;
            o0.x = fmaxf(acc[i][0] + b[0], 0.f);
            o0.y = fmaxf(acc[i][1] + b[1], 0.f);
            o0.z = fmaxf(acc[i][2] + b[2], 0.f);
            o0.w = fmaxf(acc[i][3] + b[3], 0.f);
            o1.x = fmaxf(acc[i][4] + b[4], 0.f);
            o1.y = fmaxf(acc[i][5] + b[5], 0.f);
            o1.z = fmaxf(acc[i][6] + b[6], 0.f);
            o1.w = fmaxf(acc[i][7] + b[7], 0.f);
            *(float4*)(out + (size_t)r * HID + cbase)     = o0;
            *(float4*)(out + (size_t)r * HID + cbase + 4) = o1;
        }
    }
}

extern "C" void kernel_launch(void* const* d_in, const int* in_sizes, int n_in,
                              void* d_out, int out_size) {
    const float* x_user   = (const float*)d_in[0];
    const float* x_book   = (const float*)d_in[1];
    const int*   edge_src = (const int*)  d_in[2];
    const int*   edge_dst = (const int*)  d_in[3];
    const float* Wl       = (const float*)d_in[4];
    const float* bl       = (const float*)d_in[5];
    const float* Wr       = (const float*)d_in[6];
    float* out = (float*)d_out;

    zero_kernel<<<1024, 256>>>();
    // Pass 1: user -> book. Working set x_user (51MB) + g_sum_book (26MB) fits L2.
    scatter_dir_kernel<<<8192, 256>>>(x_user, edge_src, edge_dst, /*dir=*/0);
    // Pass 2: book -> user. Working set x_book (26MB) + g_sum_user (51MB) fits L2.
    scatter_dir_kernel<<<8192, 256>>>(x_book, edge_dst, edge_src, /*dir=*/1);
    int gemm_blocks = (N_TOT + TM - 1) / TM;
    gemm_kernel<<<gemm_blocks, GTHREADS>>>(x_user, x_book, Wl, Wr, bl, out);
}